// round 10
// baseline (speedup 1.0000x reference)
#include <cuda_runtime.h>
#include <math.h>

#define K 64
#define TMAX 512
#define BMAX 1024
#define NEGV (-10000.0f)

// transT[j][i] = trans[i][j] (log_softmax result, transposed)
__device__ float g_transT[K * K];
// alpha_t rows: slot (t-1) holds alpha after step t.  134 MB scratch.
__device__ float g_alpha[(size_t)BMAX * TMAX * K];
// Final argmax state per batch
__device__ int g_last[BMAX];

__device__ __forceinline__ unsigned long long addx2(unsigned long long a,
                                                    unsigned long long b) {
    unsigned long long r;
    asm("add.rn.f32x2 %0, %1, %2;" : "=l"(r) : "l"(a), "l"(b));
    return r;
}
__device__ __forceinline__ float lo32(unsigned long long v) {
    return __uint_as_float((unsigned)v);
}
__device__ __forceinline__ float hi32(unsigned long long v) {
    return __uint_as_float((unsigned)(v >> 32));
}

// ---------------------------------------------------------------------------
// Kernel 1: trans = log_softmax(A + inv_mask * NEG), stored transposed.
// grid=64 (block per row i), 64 threads. Every block checks ALL of p1 for the
// mask property -> identical verdict in every block. expf parallel across
// threads; the exp-sum is done serially by thread 0 in j-order 0..63 (same FP
// order as the previous passing version).
// ---------------------------------------------------------------------------
__global__ void __launch_bounds__(K) trans_kernel(
    const unsigned int* __restrict__ p1,
    const unsigned int* __restrict__ p2) {
    __shared__ int s_p1_is_mask;
    __shared__ float s_x[K];
    __shared__ float s_e[K];
    __shared__ float s_red[K];
    __shared__ float s_ls;

    const int i = blockIdx.x;   // row
    const int j = threadIdx.x;  // col

    if (j == 0) s_p1_is_mask = 1;
    __syncthreads();

    int ok = 1;
#pragma unroll
    for (int c = 0; c < K; c++) {
        ok &= (p1[j * K + c] <= 1u);
    }
    if (!ok) atomicAnd(&s_p1_is_mask, 0);
    __syncthreads();

    const float* A;
    const int* inv_mask;
    if (s_p1_is_mask) {
        inv_mask = (const int*)p1;
        A = (const float*)p2;
    } else {
        inv_mask = (const int*)p2;
        A = (const float*)p1;
    }

    float x = A[i * K + j] + (inv_mask[i * K + j] ? NEGV : 0.0f);
    s_x[j] = x;
    s_red[j] = x;
    __syncthreads();
    // max reduce (fmaxf is order-independent)
#pragma unroll
    for (int off = 32; off > 0; off >>= 1) {
        if (j < off) s_red[j] = fmaxf(s_red[j], s_red[j + off]);
        __syncthreads();
    }
    float m = s_red[0];

    s_e[j] = expf(x - m);
    __syncthreads();
    if (j == 0) {
        float s = 0.0f;
#pragma unroll
        for (int c = 0; c < K; c++) s += s_e[c];   // serial, j-order (matches prior)
        s_ls = logf(s);
    }
    __syncthreads();

    g_transT[j * K + i] = (x - m) - s_ls;
}

// ---------------------------------------------------------------------------
// Kernel 2: forward pass, MAX-ONLY. One block per batch, 64 threads
// (thread = state j).
//  - transT row j packed into 32 u64 regs (f32x2 pairs)
//  - packed add.rn.f32x2 (bit-identical to scalar FADD.rn)
//  - fmaxf tree (order-independent, exact)
//  - unary register pipeline 8 deep (LDG issued 8 steps before use)
//  - alpha rows streamed to g_alpha for the backward pass
// ---------------------------------------------------------------------------
__global__ void __launch_bounds__(K, 8) viterbi_fwd(
    const float* __restrict__ unary,
    const int* __restrict__ lengths,
    int T) {
    __shared__ __align__(16) float s_alpha[2][K];

    const int b = blockIdx.x;
    const int j = threadIdx.x;

    int len = lengths[b];
    if (len > T) len = T;
    if (len > TMAX) len = TMAX;
    if (len < 1) len = 1;

    // transT row j -> 32 packed u64 regs
    unsigned long long rtp[32];
    {
        const ulonglong2* r2 = (const ulonglong2*)(g_transT + j * K);
#pragma unroll
        for (int p = 0; p < 16; p++) {
            ulonglong2 v = r2[p];
            rtp[2 * p]     = v.x;
            rtp[2 * p + 1] = v.y;
        }
    }

    s_alpha[0][j] = (j == 1) ? 0.0f : NEGV;   // GO frame
    __syncthreads();

    const float* ub = unary + (size_t)b * T * K;
    float* ab = g_alpha + (size_t)b * TMAX * K;
    int pp = 0;

    // unary pipeline: u[q] holds unary for step t = tb + q (index (t-1)*K + j)
    float u[8];
#pragma unroll
    for (int q = 0; q < 8; q++) {
        u[q] = (q + 1 <= len) ? ub[q * K + j] : 0.0f;
    }

    for (int tb = 1; tb <= len; tb += 8) {
#pragma unroll
        for (int q = 0; q < 8; q++) {
            int t = tb + q;
            if (t <= len) {   // warp-uniform
                const ulonglong2* al2 = (const ulonglong2*)s_alpha[pp];

                float pm[16];
#pragma unroll
                for (int p = 0; p < 16; p++) {
                    ulonglong2 av = al2[p];
                    unsigned long long s0 = addx2(av.x, rtp[2 * p]);
                    unsigned long long s1 = addx2(av.y, rtp[2 * p + 1]);
                    pm[p] = fmaxf(fmaxf(lo32(s0), hi32(s0)),
                                  fmaxf(lo32(s1), hi32(s1)));
                }
#pragma unroll
                for (int off = 8; off > 0; off >>= 1) {
#pragma unroll
                    for (int p = 0; p < 8; p++) {
                        if (p < off) pm[p] = fmaxf(pm[p], pm[p + off]);
                    }
                }

                float anew = pm[0] + u[q];
                s_alpha[pp ^ 1][j] = anew;
                ab[(size_t)(t - 1) * K + j] = anew;

                // prefetch unary for step t+8
                int tn = t + 8;
                u[q] = (tn <= len) ? ub[(tn - 1) * K + j] : 0.0f;

                __syncthreads();
                pp ^= 1;
            }
        }
    }

    // final argmax over states (first occurrence)
    if (j == 0) {
        float best = s_alpha[pp][0];
        int bi = 0;
#pragma unroll
        for (int i = 1; i < K; i++) {
            float v = s_alpha[pp][i];
            if (v > best) { best = v; bi = i; }
        }
        g_last[b] = bi;
    }
}

// ---------------------------------------------------------------------------
// Kernel 3: backward pass. One WARP per batch. Recomputes the needed
// backpointer per step: prev = argmax_i(alpha[t-1][i] + trans[i][tag]).
// FADDs bit-identical to reference; first-occurrence ties via monotonic
// float->u32 key + reduce_max + ballot + ffs (lowest i wins).
// Alpha rows register-prefetched 8 rows ahead.
// ---------------------------------------------------------------------------
__global__ void __launch_bounds__(32) viterbi_bwd(
    const int* __restrict__ lengths,
    float* __restrict__ out,
    int T) {
    __shared__ float s_tT[K * K];   // transT, 16KB

    const int b = blockIdx.x;
    const int k = threadIdx.x;

    int len = lengths[b];
    if (len > T) len = T;
    if (len > TMAX) len = TMAX;
    if (len < 1) len = 1;

    {
        const float4* src = (const float4*)g_transT;
        float4* dst = (float4*)s_tT;
        for (int i = k; i < K * K / 4; i += 32) {
            dst[i] = src[i];
        }
    }

    const int last = g_last[b];
    float* ob = out + (size_t)b * T;
    const float lastf = (float)last;

    for (int i = len - 1 + k; i < T; i += 32) {
        ob[i] = lastf;
    }
    __syncwarp();

    const float* ab = g_alpha + (size_t)b * TMAX * K;
    int cur = last;
    int t = len;

    float alo[8], ahi[8];
#pragma unroll
    for (int q = 0; q < 8; q++) {
        int r = t - 2 - q;
        const float* p = ab + (size_t)(r >= 0 ? r : 0) * K;
        alo[q] = p[k];
        ahi[q] = p[k + 32];
    }

    while (t >= 2) {
        float plo[8], phi[8];
#pragma unroll
        for (int q = 0; q < 8; q++) {
            int r = t - 10 - q;
            const float* p = ab + (size_t)(r >= 0 ? r : 0) * K;
            plo[q] = p[k];
            phi[q] = p[k + 32];
        }

#pragma unroll
        for (int q = 0; q < 8; q++) {
            if (t - q >= 2) {
                float tlo = s_tT[cur * K + k];
                float thi = s_tT[cur * K + k + 32];
                float f1 = alo[q] + tlo;
                float f2 = ahi[q] + thi;
                unsigned u1 = __float_as_uint(f1);
                u1 ^= ((unsigned)((int)u1 >> 31)) | 0x80000000u;
                unsigned u2 = __float_as_uint(f2);
                u2 ^= ((unsigned)((int)u2 >> 31)) | 0x80000000u;
                unsigned um = u1 > u2 ? u1 : u2;
                unsigned vm = __reduce_max_sync(0xffffffffu, um);
                unsigned b1 = __ballot_sync(0xffffffffu, u1 == vm);
                unsigned b2 = __ballot_sync(0xffffffffu, u2 == vm);
                cur = b1 ? (__ffs(b1) - 1) : (__ffs(b2) + 31);
                ob[t - q - 2] = (float)cur;
            }
        }

        t -= 8;
#pragma unroll
        for (int q = 0; q < 8; q++) {
            alo[q] = plo[q];
            ahi[q] = phi[q];
        }
    }
}

extern "C" void kernel_launch(void* const* d_in, const int* in_sizes, int n_in,
                              void* d_out, int out_size) {
    // Bind inputs by SIZE, not position.
    int idx_unary = 0;
    long long max_sz = -1;
    for (int i = 0; i < n_in; i++) {
        if ((long long)in_sizes[i] > max_sz) { max_sz = in_sizes[i]; idx_unary = i; }
    }
    int idx_sq[2] = {-1, -1};
    int idx_len = -1;
    for (int i = 0; i < n_in; i++) {
        if (i == idx_unary) continue;
        if (in_sizes[i] == K * K) {
            if (idx_sq[0] < 0) idx_sq[0] = i; else idx_sq[1] = i;
        } else {
            idx_len = i;
        }
    }

    const float* unary   = (const float*)d_in[idx_unary];
    const int*   lengths = (const int*)d_in[idx_len];
    const unsigned int* p1 = (const unsigned int*)d_in[idx_sq[0]];
    const unsigned int* p2 = (const unsigned int*)d_in[idx_sq[1]];
    float* out = (float*)d_out;

    int B = in_sizes[idx_len];                                // 1024
    int T = (int)(in_sizes[idx_unary] / ((long long)B * K));  // 512
    if (B > BMAX) B = BMAX;

    trans_kernel<<<K, K>>>(p1, p2);
    viterbi_fwd<<<B, K>>>(unary, lengths, T);
    viterbi_bwd<<<B, 32>>>(lengths, out, T);
}